// round 5
// baseline (speedup 1.0000x reference)
#include <cuda_runtime.h>
#include <math.h>

#define BN    2048
#define CIN   256
#define NHID  512
#define NF    112
#define KC    112
#define NL    50
#define MC    100
#define NOUTC 200

// 1 = jax_threefry_partitionable (modern default); 0 = legacy threefry
#define PRNG_MODE 1

// ---------------- scratch (device globals; no allocation) ----------------
__device__ float g_h0[BN * NHID];
__device__ float g_h1[BN * NHID];
__device__ float g_inter[BN * NF];
__device__ float g_base[(size_t)KC * BN * NL];           // 45.9 MB
__device__ float g_logits[(size_t)BN * MC * NOUTC];      // 163.8 MB
__device__ __align__(16) unsigned g_cbits[BN * MC * 4];  // packed c_hard bits
__device__ unsigned g_keys[KC * 2];

// ---------------- Threefry-2x32 (matches JAX) ----------------
__device__ __forceinline__ void tf2x32(unsigned k0, unsigned k1,
                                       unsigned c0, unsigned c1,
                                       unsigned& o0, unsigned& o1) {
    unsigned ks2 = 0x1BD11BDAu ^ k0 ^ k1;
    unsigned x0 = c0 + k0, x1 = c1 + k1;
#define TF_R(r) { x0 += x1; x1 = (x1 << (r)) | (x1 >> (32 - (r))); x1 ^= x0; }
    TF_R(13) TF_R(15) TF_R(26) TF_R(6)
    x0 += k1;  x1 += ks2 + 1u;
    TF_R(17) TF_R(29) TF_R(16) TF_R(24)
    x0 += ks2; x1 += k0 + 2u;
    TF_R(13) TF_R(15) TF_R(26) TF_R(6)
    x0 += k0;  x1 += k1 + 3u;
    TF_R(17) TF_R(29) TF_R(16) TF_R(24)
    x0 += k1;  x1 += ks2 + 4u;
    TF_R(13) TF_R(15) TF_R(26) TF_R(6)
    x0 += ks2; x1 += k0 + 5u;
#undef TF_R
    o0 = x0; o1 = x1;
}

__device__ __forceinline__ float jax_uniform(unsigned k0, unsigned k1, unsigned t) {
    unsigned o0, o1, bits;
#if PRNG_MODE == 1
    tf2x32(k0, k1, 0u, t, o0, o1); bits = o0 ^ o1;
#else
    const unsigned half = (BN * MC) / 2u;
    if (t < half) { tf2x32(k0, k1, t, t + half, o0, o1); bits = o0; }
    else          { tf2x32(k0, k1, t - half, t, o0, o1); bits = o1; }
#endif
    return __uint_as_float((bits >> 9) | 0x3F800000u) - 1.0f;
}

// ---------------- init: zero cbits, derive 112 subkeys ----------------
__global__ void init_kernel() {
    int idx = blockIdx.x * blockDim.x + threadIdx.x;
    for (int i = idx; i < BN * MC * 4; i += gridDim.x * blockDim.x) g_cbits[i] = 0u;
    if (idx == 0) {
        unsigned k0 = 0u, k1 = 42u;            // jax.random.key(42)
        for (int i = 0; i < KC; i++) {
#if PRNG_MODE == 1
            unsigned n0, n1, s0, s1;
            tf2x32(k0, k1, 0u, 0u, n0, n1);    // new key
            tf2x32(k0, k1, 0u, 1u, s0, s1);    // subkey
            g_keys[2 * i] = s0; g_keys[2 * i + 1] = s1;
            k0 = n0; k1 = n1;
#else
            unsigned a0, b0, a1, b1;
            tf2x32(k0, k1, 0u, 2u, a0, b0);
            tf2x32(k0, k1, 1u, 3u, a1, b1);
            g_keys[2 * i] = b0; g_keys[2 * i + 1] = b1;
            k0 = a0; k1 = a1;
#endif
        }
    }
}

// ---------------- tiled fp32 SGEMM: C = act(A@B + bias), batched via z ----------------
__global__ void __launch_bounds__(256) sgemm_bias(
    const float* __restrict__ A, const float* __restrict__ Bm,
    const float* __restrict__ bias, float* __restrict__ C,
    int M, int N, int Kd, int act,
    long sA, long sB, long sBias, long sC)
{
    A    += (size_t)blockIdx.z * sA;
    Bm   += (size_t)blockIdx.z * sB;
    bias += (size_t)blockIdx.z * sBias;
    C    += (size_t)blockIdx.z * sC;

    __shared__ float As[16][65];
    __shared__ float Bs[16][65];
    const int bm = blockIdx.y * 64;
    const int bn = blockIdx.x * 64;
    const int tid = threadIdx.x;
    const int tr = tid / 16, tc = tid % 16;

    float acc[4][4];
#pragma unroll
    for (int i = 0; i < 4; i++)
#pragma unroll
        for (int j = 0; j < 4; j++) acc[i][j] = 0.f;

    for (int k0 = 0; k0 < Kd; k0 += 16) {
        for (int l = tid; l < 64 * 16; l += 256) {
            int m = l / 16, k = l % 16;
            As[k][m] = A[(size_t)(bm + m) * Kd + k0 + k];
        }
        for (int l = tid; l < 16 * 64; l += 256) {
            int k = l / 64, n = l % 64;
            Bs[k][n] = (bn + n < N) ? Bm[(size_t)(k0 + k) * N + bn + n] : 0.f;
        }
        __syncthreads();
#pragma unroll
        for (int k = 0; k < 16; k++) {
            float a[4], b[4];
#pragma unroll
            for (int i = 0; i < 4; i++) a[i] = As[k][tr * 4 + i];
#pragma unroll
            for (int j = 0; j < 4; j++) b[j] = Bs[k][tc * 4 + j];
#pragma unroll
            for (int i = 0; i < 4; i++)
#pragma unroll
                for (int j = 0; j < 4; j++)
                    acc[i][j] = fmaf(a[i], b[j], acc[i][j]);
        }
        __syncthreads();
    }
#pragma unroll
    for (int i = 0; i < 4; i++) {
        int m = bm + tr * 4 + i;
#pragma unroll
        for (int j = 0; j < 4; j++) {
            int n = bn + tc * 4 + j;
            if (n < N) {
                float v = acc[i][j] + bias[n];
                if (act) v = (v > 0.f) ? v : 0.01f * v;
                C[(size_t)m * N + n] = v;
            }
        }
    }
}

// ---------------- concept step i: fused recurrence + sigmoid + bernoulli ----------------
__global__ void __launch_bounds__(256) step_kernel(
    int i,
    const float* __restrict__ pW2, const float* __restrict__ pb2,
    float* __restrict__ c_prob, float* __restrict__ c_hard)
{
    __shared__ __align__(16) float baseS[4][52];
    __shared__ float W2S[52];
    extern __shared__ float Ws[];   // i rows x 52 floats (cols 50,51 = 0)

    const int tid  = threadIdx.x;
    const int idx  = blockIdx.x * 256 + tid;
    const int b0   = (blockIdx.x * 256) / MC;
    const int b    = idx / MC;
    const int m    = idx - b * MC;

    for (int l = tid; l < 4 * 52; l += 256) {
        int d = l / 52, h = l - d * 52;
        int bb = b0 + d; if (bb > BN - 1) bb = BN - 1;
        baseS[d][h] = (h < NL) ? g_base[((size_t)i * BN + bb) * NL + h] : 0.f;
    }
    if (tid < 52) W2S[tid] = (tid < NL) ? pW2[i * NL + tid] : 0.f;
    // Ws is pre-staged by host via separate loads? No: load W1 tail here.
    __syncthreads();   // baseS/W2S ready; Ws loaded below before use

    // load this thread's bit history
    uint4 cbv = ((const uint4*)g_cbits)[idx];
    unsigned cb[4] = {cbv.x, cbv.y, cbv.z, cbv.w};

    float4 hp[13];
    const int db = b - b0;
#pragma unroll
    for (int q = 0; q < 13; q++) hp[q] = *(const float4*)&baseS[db][4 * q];

    for (int j = 0; j < i; j++) {
        float cj = ((cb[j >> 5] >> (j & 31)) & 1u) ? 1.f : 0.f;
        const float4* wr = (const float4*)(Ws + j * 52);
#pragma unroll
        for (int q = 0; q < 13; q++) {
            float4 w = wr[q];
            hp[q].x = fmaf(cj, w.x, hp[q].x);
            hp[q].y = fmaf(cj, w.y, hp[q].y);
            hp[q].z = fmaf(cj, w.z, hp[q].z);
            hp[q].w = fmaf(cj, w.w, hp[q].w);
        }
    }

    float z = 0.f;
#pragma unroll
    for (int q = 0; q < 13; q++) {
        float v;
        v = hp[q].x; v = (v > 0.f) ? v : 0.01f * v; z = fmaf(v, W2S[4 * q + 0], z);
        v = hp[q].y; v = (v > 0.f) ? v : 0.01f * v; z = fmaf(v, W2S[4 * q + 1], z);
        v = hp[q].z; v = (v > 0.f) ? v : 0.01f * v; z = fmaf(v, W2S[4 * q + 2], z);
        v = hp[q].w; v = (v > 0.f) ? v : 0.01f * v; z = fmaf(v, W2S[4 * q + 3], z);
    }
    z += pb2[i];
    float p = 1.f / (1.f + expf(-z));

    float u = jax_uniform(g_keys[2 * i], g_keys[2 * i + 1], (unsigned)idx);
    unsigned sbit = (u < p) ? 1u : 0u;

    size_t o = ((size_t)b * KC + i) * MC + m;
    c_prob[o] = p;
    c_hard[o] = (float)sbit;
    g_cbits[idx * 4 + (i >> 5)] = cb[i >> 5] | (sbit << (i & 31));
}

// loads W1 tail for step i into dynamic smem, then runs step body — combined above.
// (Ws loading kernel-side:)
__global__ void __launch_bounds__(256) step_kernel_full(
    int i,
    const float* __restrict__ pW1, const float* __restrict__ pW2,
    const float* __restrict__ pb2,
    float* __restrict__ c_prob, float* __restrict__ c_hard)
{
    __shared__ __align__(16) float baseS[4][52];
    __shared__ float W2S[52];
    extern __shared__ float Ws[];

    const int tid  = threadIdx.x;
    const int idx  = blockIdx.x * 256 + tid;
    const int b0   = (blockIdx.x * 256) / MC;
    const int b    = idx / MC;
    const int m    = idx - b * MC;

    for (int l = tid; l < 4 * 52; l += 256) {
        int d = l / 52, h = l - d * 52;
        int bb = b0 + d; if (bb > BN - 1) bb = BN - 1;
        baseS[d][h] = (h < NL) ? g_base[((size_t)i * BN + bb) * NL + h] : 0.f;
    }
    if (tid < 52) W2S[tid] = (tid < NL) ? pW2[i * NL + tid] : 0.f;
    for (int l = tid; l < i * 52; l += 256) {
        int j = l / 52, h = l - j * 52;
        Ws[l] = (h < NL) ? pW1[((size_t)i * (NF + KC) + NF + j) * NL + h] : 0.f;
    }
    __syncthreads();

    uint4 cbv = ((const uint4*)g_cbits)[idx];
    unsigned cb[4] = {cbv.x, cbv.y, cbv.z, cbv.w};

    float4 hp[13];
    const int db = b - b0;
#pragma unroll
    for (int q = 0; q < 13; q++) hp[q] = *(const float4*)&baseS[db][4 * q];

    for (int j = 0; j < i; j++) {
        float cj = ((cb[j >> 5] >> (j & 31)) & 1u) ? 1.f : 0.f;
        const float4* wr = (const float4*)(Ws + j * 52);
#pragma unroll
        for (int q = 0; q < 13; q++) {
            float4 w = wr[q];
            hp[q].x = fmaf(cj, w.x, hp[q].x);
            hp[q].y = fmaf(cj, w.y, hp[q].y);
            hp[q].z = fmaf(cj, w.z, hp[q].z);
            hp[q].w = fmaf(cj, w.w, hp[q].w);
        }
    }

    float z = 0.f;
#pragma unroll
    for (int q = 0; q < 13; q++) {
        float v;
        v = hp[q].x; v = (v > 0.f) ? v : 0.01f * v; z = fmaf(v, W2S[4 * q + 0], z);
        v = hp[q].y; v = (v > 0.f) ? v : 0.01f * v; z = fmaf(v, W2S[4 * q + 1], z);
        v = hp[q].z; v = (v > 0.f) ? v : 0.01f * v; z = fmaf(v, W2S[4 * q + 2], z);
        v = hp[q].w; v = (v > 0.f) ? v : 0.01f * v; z = fmaf(v, W2S[4 * q + 3], z);
    }
    z += pb2[i];
    float p = 1.f / (1.f + expf(-z));

    float u = jax_uniform(g_keys[2 * i], g_keys[2 * i + 1], (unsigned)idx);
    unsigned sbit = (u < p) ? 1u : 0u;

    size_t o = ((size_t)b * KC + i) * MC + m;
    c_prob[o] = p;
    c_hard[o] = (float)sbit;
    g_cbits[idx * 4 + (i >> 5)] = cb[i >> 5] | (sbit << (i & 31));
}

// ---------------- head GEMM: logits = bits @ head_W + head_b ----------------
__global__ void __launch_bounds__(256) head_gemm(
    const float* __restrict__ Bm, const float* __restrict__ bias)
{
    __shared__ float As[16][65];
    __shared__ float Bs[16][65];
    const int bm = blockIdx.y * 64;
    const int bn = blockIdx.x * 64;
    const int tid = threadIdx.x;
    const int tr = tid / 16, tc = tid % 16;
    const int N = NOUTC, Kd = KC;

    float acc[4][4];
#pragma unroll
    for (int i = 0; i < 4; i++)
#pragma unroll
        for (int j = 0; j < 4; j++) acc[i][j] = 0.f;

    for (int k0 = 0; k0 < Kd; k0 += 16) {
        for (int l = tid; l < 64 * 16; l += 256) {
            int m = l / 16, k = l % 16;
            int kk = k0 + k;
            unsigned w = g_cbits[(size_t)(bm + m) * 4 + (kk >> 5)];
            As[k][m] = ((w >> (kk & 31)) & 1u) ? 1.f : 0.f;
        }
        for (int l = tid; l < 16 * 64; l += 256) {
            int k = l / 64, n = l % 64;
            Bs[k][n] = (bn + n < N) ? Bm[(size_t)(k0 + k) * N + bn + n] : 0.f;
        }
        __syncthreads();
#pragma unroll
        for (int k = 0; k < 16; k++) {
            float a[4], b[4];
#pragma unroll
            for (int i = 0; i < 4; i++) a[i] = As[k][tr * 4 + i];
#pragma unroll
            for (int j = 0; j < 4; j++) b[j] = Bs[k][tc * 4 + j];
#pragma unroll
            for (int i = 0; i < 4; i++)
#pragma unroll
                for (int j = 0; j < 4; j++)
                    acc[i][j] = fmaf(a[i], b[j], acc[i][j]);
        }
        __syncthreads();
    }
#pragma unroll
    for (int i = 0; i < 4; i++) {
        int m = bm + tr * 4 + i;
#pragma unroll
        for (int j = 0; j < 4; j++) {
            int n = bn + tc * 4 + j;
            if (n < N) g_logits[(size_t)m * N + n] = acc[i][j] + bias[n];
        }
    }
}

// ---------------- softmax over o, mean over m, log ----------------
__global__ void __launch_bounds__(256) softmax_kernel(float* __restrict__ yp)
{
    __shared__ float red[256];
    const int b = blockIdx.x;
    const int tid = threadIdx.x;
    float acc = 0.f;
    for (int m = 0; m < MC; m++) {
        const float* row = g_logits + ((size_t)b * MC + m) * NOUTC;
        float v = (tid < NOUTC) ? row[tid] : -1e30f;
        red[tid] = v; __syncthreads();
        for (int s = 128; s > 0; s >>= 1) {
            if (tid < s) red[tid] = fmaxf(red[tid], red[tid + s]);
            __syncthreads();
        }
        float rm = red[0]; __syncthreads();
        float e = (tid < NOUTC) ? expf(v - rm) : 0.f;
        red[tid] = e; __syncthreads();
        for (int s = 128; s > 0; s >>= 1) {
            if (tid < s) red[tid] += red[tid + s];
            __syncthreads();
        }
        float s0 = red[0]; __syncthreads();
        acc += e / s0;
    }
    if (tid < NOUTC) yp[(size_t)b * NOUTC + tid] = logf(acc * (1.f / MC) + 1e-6f);
}

// ---------------- launch ----------------
extern "C" void kernel_launch(void* const* d_in, const int* in_sizes, int n_in,
                              void* d_out, int out_size) {
    const float* x     = (const float*)d_in[0];
    const float* Win   = (const float*)d_in[1];
    const float* binp  = (const float*)d_in[2];
    const float* Wh    = (const float*)d_in[3];
    const float* bh    = (const float*)d_in[4];
    const float* Wout  = (const float*)d_in[5];
    const float* bout  = (const float*)d_in[6];
    const float* pW1   = (const float*)d_in[7];
    const float* pb1   = (const float*)d_in[8];
    const float* pW2   = (const float*)d_in[9];
    const float* pb2   = (const float*)d_in[10];
    const float* hW    = (const float*)d_in[11];
    const float* hb    = (const float*)d_in[12];

    float* out    = (float*)d_out;
    float* c_prob = out;
    float* ypred  = out + (size_t)BN * KC * MC;
    float* c_hard = ypred + (size_t)BN * NOUTC;

    float *h0, *h1, *inter, *base;
    cudaGetSymbolAddress((void**)&h0,    g_h0);
    cudaGetSymbolAddress((void**)&h1,    g_h1);
    cudaGetSymbolAddress((void**)&inter, g_inter);
    cudaGetSymbolAddress((void**)&base,  g_base);

    init_kernel<<<256, 256>>>();

    // encoder
    sgemm_bias<<<dim3(NHID/64, BN/64, 1), 256>>>(x,  Win, binp, h0, BN, NHID, CIN,  1, 0,0,0,0);
    sgemm_bias<<<dim3(NHID/64, BN/64, 1), 256>>>(h0, Wh + 0*NHID*NHID, bh + 0*NHID, h1, BN, NHID, NHID, 1, 0,0,0,0);
    sgemm_bias<<<dim3(NHID/64, BN/64, 1), 256>>>(h1, Wh + 1*NHID*NHID, bh + 1*NHID, h0, BN, NHID, NHID, 1, 0,0,0,0);
    sgemm_bias<<<dim3(NHID/64, BN/64, 1), 256>>>(h0, Wh + 2*NHID*NHID, bh + 2*NHID, h1, BN, NHID, NHID, 1, 0,0,0,0);
    sgemm_bias<<<dim3(NHID/64, BN/64, 1), 256>>>(h1, Wh + 3*NHID*NHID, bh + 3*NHID, h0, BN, NHID, NHID, 1, 0,0,0,0);
    sgemm_bias<<<dim3(2, BN/64, 1), 256>>>(h0, Wout, bout, inter, BN, NF, NHID, 0, 0,0,0,0);

    // all base vectors: base[i] = inter @ W1[i][:NF] + b1[i]  (batched over i)
    sgemm_bias<<<dim3(1, BN/64, KC), 256>>>(inter, pW1, pb1, base, BN, NL, NF, 0,
                                            0, (long)(NF + KC) * NL, NL, (long)BN * NL);

    // 112 sequential concept steps
    for (int i = 0; i < KC; i++) {
        size_t shm = (size_t)i * 52 * sizeof(float);
        step_kernel_full<<<(BN * MC) / 256, 256, shm>>>(i, pW1, pW2, pb2, c_prob, c_hard);
    }

    // head
    head_gemm<<<dim3((NOUTC + 63) / 64, (BN * MC) / 64, 1), 256>>>(hW, hb);
    softmax_kernel<<<BN, 256>>>(ypred);
}

// round 6
// speedup vs baseline: 1.4406x; 1.4406x over previous
#include <cuda_runtime.h>
#include <math.h>

#define BN    2048
#define CIN   256
#define NHID  512
#define NF    112
#define KC    112
#define NL    50
#define MC    100
#define NOUTC 200

// ---------------- scratch (device globals; no allocation) ----------------
__device__ float g_h0[BN * NHID];
__device__ float g_h1[BN * NHID];
__device__ float g_inter[BN * NF];
__device__ float g_base[(size_t)KC * BN * NL];           // 45.9 MB
__device__ float g_logits[(size_t)BN * MC * NOUTC];      // 163.8 MB
__device__ __align__(16) unsigned g_cbits[BN * MC * 4];  // packed c_hard bits
__device__ unsigned g_keys[KC * 2];

// ---------------- Threefry-2x32 (matches JAX) ----------------
__device__ __forceinline__ void tf2x32(unsigned k0, unsigned k1,
                                       unsigned c0, unsigned c1,
                                       unsigned& o0, unsigned& o1) {
    unsigned ks2 = 0x1BD11BDAu ^ k0 ^ k1;
    unsigned x0 = c0 + k0, x1 = c1 + k1;
#define TF_R(r) { x0 += x1; x1 = (x1 << (r)) | (x1 >> (32 - (r))); x1 ^= x0; }
    TF_R(13) TF_R(15) TF_R(26) TF_R(6)
    x0 += k1;  x1 += ks2 + 1u;
    TF_R(17) TF_R(29) TF_R(16) TF_R(24)
    x0 += ks2; x1 += k0 + 2u;
    TF_R(13) TF_R(15) TF_R(26) TF_R(6)
    x0 += k0;  x1 += k1 + 3u;
    TF_R(17) TF_R(29) TF_R(16) TF_R(24)
    x0 += k1;  x1 += ks2 + 4u;
    TF_R(13) TF_R(15) TF_R(26) TF_R(6)
    x0 += ks2; x1 += k0 + 5u;
#undef TF_R
    o0 = x0; o1 = x1;
}

__device__ __forceinline__ float jax_uniform(unsigned k0, unsigned k1, unsigned t) {
    unsigned o0, o1, bits;
    tf2x32(k0, k1, 0u, t, o0, o1); bits = o0 ^ o1;
    return __uint_as_float((bits >> 9) | 0x3F800000u) - 1.0f;
}

// ---------------- init: zero cbits, derive 112 subkeys ----------------
__global__ void init_kernel() {
    int idx = blockIdx.x * blockDim.x + threadIdx.x;
    for (int i = idx; i < BN * MC * 4; i += gridDim.x * blockDim.x) g_cbits[i] = 0u;
    if (idx == 0) {
        unsigned k0 = 0u, k1 = 42u;            // jax.random.key(42)
        for (int i = 0; i < KC; i++) {
            unsigned n0, n1, s0, s1;
            tf2x32(k0, k1, 0u, 0u, n0, n1);    // new key
            tf2x32(k0, k1, 0u, 1u, s0, s1);    // subkey
            g_keys[2 * i] = s0; g_keys[2 * i + 1] = s1;
            k0 = n0; k1 = n1;
        }
    }
}

// ---------------- original 64x64 SGEMM (kept bit-identical; used for base GEMM) ----
__global__ void __launch_bounds__(256) sgemm_bias(
    const float* __restrict__ A, const float* __restrict__ Bm,
    const float* __restrict__ bias, float* __restrict__ C,
    int M, int N, int Kd, int act,
    long sA, long sB, long sBias, long sC)
{
    A    += (size_t)blockIdx.z * sA;
    Bm   += (size_t)blockIdx.z * sB;
    bias += (size_t)blockIdx.z * sBias;
    C    += (size_t)blockIdx.z * sC;

    __shared__ float As[16][65];
    __shared__ float Bs[16][65];
    const int bm = blockIdx.y * 64;
    const int bn = blockIdx.x * 64;
    const int tid = threadIdx.x;
    const int tr = tid / 16, tc = tid % 16;

    float acc[4][4];
#pragma unroll
    for (int i = 0; i < 4; i++)
#pragma unroll
        for (int j = 0; j < 4; j++) acc[i][j] = 0.f;

    for (int k0 = 0; k0 < Kd; k0 += 16) {
        for (int l = tid; l < 64 * 16; l += 256) {
            int m = l / 16, k = l % 16;
            As[k][m] = A[(size_t)(bm + m) * Kd + k0 + k];
        }
        for (int l = tid; l < 16 * 64; l += 256) {
            int k = l / 64, n = l % 64;
            Bs[k][n] = (bn + n < N) ? Bm[(size_t)(k0 + k) * N + bn + n] : 0.f;
        }
        __syncthreads();
#pragma unroll
        for (int k = 0; k < 16; k++) {
            float a[4], b[4];
#pragma unroll
            for (int i = 0; i < 4; i++) a[i] = As[k][tr * 4 + i];
#pragma unroll
            for (int j = 0; j < 4; j++) b[j] = Bs[k][tc * 4 + j];
#pragma unroll
            for (int i = 0; i < 4; i++)
#pragma unroll
                for (int j = 0; j < 4; j++)
                    acc[i][j] = fmaf(a[i], b[j], acc[i][j]);
        }
        __syncthreads();
    }
#pragma unroll
    for (int i = 0; i < 4; i++) {
        int m = bm + tr * 4 + i;
#pragma unroll
        for (int j = 0; j < 4; j++) {
            int n = bn + tc * 4 + j;
            if (n < N) {
                float v = acc[i][j] + bias[n];
                if (act) v = (v > 0.f) ? v : 0.01f * v;
                C[(size_t)m * N + n] = v;
            }
        }
    }
}

// ---------------- double-buffered 64x64 SGEMM (encoder; same fmaf k-order) ----------
__global__ void __launch_bounds__(256) sgemm_bias_db(
    const float* __restrict__ A, const float* __restrict__ Bm,
    const float* __restrict__ bias, float* __restrict__ C,
    int M, int N, int Kd, int act)
{
    __shared__ float As[2][16][65];
    __shared__ float Bs[2][16][65];
    const int bm = blockIdx.y * 64;
    const int bn = blockIdx.x * 64;
    const int tid = threadIdx.x;
    const int tr = tid / 16, tc = tid % 16;

    float acc[4][4];
#pragma unroll
    for (int i = 0; i < 4; i++)
#pragma unroll
        for (int j = 0; j < 4; j++) acc[i][j] = 0.f;

    const int nk = Kd / 16;
    // preload tile 0
#pragma unroll
    for (int u = 0; u < 4; u++) {
        int l = tid + 256 * u; int m = l >> 4, k = l & 15;
        As[0][k][m] = A[(size_t)(bm + m) * Kd + k];
    }
#pragma unroll
    for (int u = 0; u < 4; u++) {
        int l = tid + 256 * u; int k = l >> 6, n = l & 63;
        Bs[0][k][n] = (bn + n < N) ? Bm[(size_t)k * N + bn + n] : 0.f;
    }
    __syncthreads();

    for (int t = 0; t < nk; t++) {
        const int cur = t & 1, nxt = cur ^ 1;
        float ra[4], rb[4];
        if (t + 1 < nk) {
            const int k0n = (t + 1) * 16;
#pragma unroll
            for (int u = 0; u < 4; u++) {
                int l = tid + 256 * u; int m = l >> 4, k = l & 15;
                ra[u] = A[(size_t)(bm + m) * Kd + k0n + k];
            }
#pragma unroll
            for (int u = 0; u < 4; u++) {
                int l = tid + 256 * u; int k = l >> 6, n = l & 63;
                rb[u] = (bn + n < N) ? Bm[(size_t)(k0n + k) * N + bn + n] : 0.f;
            }
        }
#pragma unroll
        for (int k = 0; k < 16; k++) {
            float a[4], b[4];
#pragma unroll
            for (int i = 0; i < 4; i++) a[i] = As[cur][k][tr * 4 + i];
#pragma unroll
            for (int j = 0; j < 4; j++) b[j] = Bs[cur][k][tc * 4 + j];
#pragma unroll
            for (int i = 0; i < 4; i++)
#pragma unroll
                for (int j = 0; j < 4; j++)
                    acc[i][j] = fmaf(a[i], b[j], acc[i][j]);
        }
        if (t + 1 < nk) {
#pragma unroll
            for (int u = 0; u < 4; u++) {
                int l = tid + 256 * u; int m = l >> 4, k = l & 15;
                As[nxt][k][m] = ra[u];
            }
#pragma unroll
            for (int u = 0; u < 4; u++) {
                int l = tid + 256 * u; int k = l >> 6, n = l & 63;
                Bs[nxt][k][n] = rb[u];
            }
        }
        __syncthreads();
    }
#pragma unroll
    for (int i = 0; i < 4; i++) {
        int m = bm + tr * 4 + i;
#pragma unroll
        for (int j = 0; j < 4; j++) {
            int n = bn + tc * 4 + j;
            if (n < N) {
                float v = acc[i][j] + bias[n];
                if (act) v = (v > 0.f) ? v : 0.01f * v;
                C[(size_t)m * N + n] = v;
            }
        }
    }
}

// ---------------- concept step i: 2 (b,m) pairs/thread, fma.rn.f32x2 ----------------
// Per-element FP ops and their order are IDENTICAL to the round-4 kernel
// (fmaf(c_j, w_h, hp_h) for j ascending, then leaky+fmaf into z for h ascending).
__global__ void __launch_bounds__(128) step2_kernel(
    int i,
    const float* __restrict__ pW1, const float* __restrict__ pW2,
    const float* __restrict__ pb2,
    float* __restrict__ c_prob, float* __restrict__ c_hard)
{
    __shared__ __align__(16) float baseS[4][52];
    __shared__ float W2S[52];
    __shared__ float b2s;
    extern __shared__ __align__(16) float Ws[];   // i rows x 52 floats (cols 50,51 = 0)

    const int tid  = threadIdx.x;
    const int idx0 = blockIdx.x * 256;            // first (b,m) index of this block
    const int b0   = idx0 / MC;
    const int p0   = idx0 + 2 * tid;
    const int p1   = p0 + 1;

    for (int l = tid; l < 4 * 52; l += 128) {
        int d = l / 52, h = l - d * 52;
        int bb = b0 + d; if (bb > BN - 1) bb = BN - 1;
        baseS[d][h] = (h < NL) ? g_base[((size_t)i * BN + bb) * NL + h] : 0.f;
    }
    if (tid < 52) W2S[tid] = (tid < NL) ? pW2[i * NL + tid] : 0.f;
    if (tid == 0) b2s = pb2[i];
    for (int l = tid; l < i * 52; l += 128) {
        int j = l / 52, h = l - j * 52;
        Ws[l] = (h < NL) ? pW1[((size_t)i * (NF + KC) + NF + j) * NL + h] : 0.f;
    }
    __syncthreads();

    const uint4 cv0 = ((const uint4*)g_cbits)[p0];
    const uint4 cv1 = ((const uint4*)g_cbits)[p1];

    const int b_0 = p0 / MC, m_0 = p0 - b_0 * MC;
    const int b_1 = p1 / MC, m_1 = p1 - b_1 * MC;
    const int db0 = b_0 - b0, db1 = b_1 - b0;

    unsigned long long hp0[26], hp1[26];
    {
        const unsigned long long* s0 = (const unsigned long long*)(&baseS[db0][0]);
        const unsigned long long* s1 = (const unsigned long long*)(&baseS[db1][0]);
#pragma unroll
        for (int r = 0; r < 26; r++) { hp0[r] = s0[r]; hp1[r] = s1[r]; }
    }

#pragma unroll
    for (int w = 0; w < 4; w++) {
        const int jrem = i - w * 32;
        if (jrem <= 0) break;
        const int jend = (jrem < 32) ? jrem : 32;
        unsigned bw0 = (w == 0) ? cv0.x : (w == 1) ? cv0.y : (w == 2) ? cv0.z : cv0.w;
        unsigned bw1 = (w == 0) ? cv1.x : (w == 1) ? cv1.y : (w == 2) ? cv1.z : cv1.w;
        const float* wrow = Ws + (size_t)w * 32 * 52;
        for (int j2 = 0; j2 < jend; j2++) {
            float c0 = (bw0 & 1u) ? 1.f : 0.f; bw0 >>= 1;
            float c1 = (bw1 & 1u) ? 1.f : 0.f; bw1 >>= 1;
            unsigned long long cc0, cc1;
            asm("mov.b64 %0, {%1, %1};" : "=l"(cc0) : "r"(__float_as_uint(c0)));
            asm("mov.b64 %0, {%1, %1};" : "=l"(cc1) : "r"(__float_as_uint(c1)));
            const ulonglong2* wr = (const ulonglong2*)(wrow + j2 * 52);
#pragma unroll
            for (int q = 0; q < 13; q++) {
                ulonglong2 wv = wr[q];
                asm("fma.rn.f32x2 %0, %1, %2, %0;" : "+l"(hp0[2*q  ]) : "l"(cc0), "l"(wv.x));
                asm("fma.rn.f32x2 %0, %1, %2, %0;" : "+l"(hp0[2*q+1]) : "l"(cc0), "l"(wv.y));
                asm("fma.rn.f32x2 %0, %1, %2, %0;" : "+l"(hp1[2*q  ]) : "l"(cc1), "l"(wv.x));
                asm("fma.rn.f32x2 %0, %1, %2, %0;" : "+l"(hp1[2*q+1]) : "l"(cc1), "l"(wv.y));
            }
        }
    }

    // epilogue: leaky + dot with W2, h ascending 0..49 (50,51 are zero-padded; skipping
    // them is exact since fmaf(v, 0, z) == z)
    float z0 = 0.f, z1 = 0.f;
#pragma unroll
    for (int r = 0; r < 25; r++) {
        unsigned lo, hi;
        asm("mov.b64 {%0, %1}, %2;" : "=r"(lo), "=r"(hi) : "l"(hp0[r]));
        float v = __uint_as_float(lo); v = (v > 0.f) ? v : 0.01f * v; z0 = fmaf(v, W2S[2*r],   z0);
        v = __uint_as_float(hi);       v = (v > 0.f) ? v : 0.01f * v; z0 = fmaf(v, W2S[2*r+1], z0);
        asm("mov.b64 {%0, %1}, %2;" : "=r"(lo), "=r"(hi) : "l"(hp1[r]));
        v = __uint_as_float(lo);       v = (v > 0.f) ? v : 0.01f * v; z1 = fmaf(v, W2S[2*r],   z1);
        v = __uint_as_float(hi);       v = (v > 0.f) ? v : 0.01f * v; z1 = fmaf(v, W2S[2*r+1], z1);
    }
    z0 += b2s; z1 += b2s;
    float pp0 = 1.f / (1.f + expf(-z0));
    float pp1 = 1.f / (1.f + expf(-z1));

    const unsigned key0 = g_keys[2 * i], key1 = g_keys[2 * i + 1];
    unsigned s0 = (jax_uniform(key0, key1, (unsigned)p0) < pp0) ? 1u : 0u;
    unsigned s1 = (jax_uniform(key0, key1, (unsigned)p1) < pp1) ? 1u : 0u;

    const size_t o0 = ((size_t)b_0 * KC + i) * MC + m_0;
    const size_t o1 = ((size_t)b_1 * KC + i) * MC + m_1;
    c_prob[o0] = pp0; c_hard[o0] = (float)s0;
    c_prob[o1] = pp1; c_hard[o1] = (float)s1;

    const int wi = i >> 5; const unsigned sh = (unsigned)(i & 31);
    unsigned old0 = (wi == 0) ? cv0.x : (wi == 1) ? cv0.y : (wi == 2) ? cv0.z : cv0.w;
    unsigned old1 = (wi == 0) ? cv1.x : (wi == 1) ? cv1.y : (wi == 2) ? cv1.z : cv1.w;
    g_cbits[p0 * 4 + wi] = old0 | (s0 << sh);
    g_cbits[p1 * 4 + wi] = old1 | (s1 << sh);
}

// ---------------- head GEMM: logits = bits @ head_W + head_b ----------------
__global__ void __launch_bounds__(256) head_gemm(
    const float* __restrict__ Bm, const float* __restrict__ bias)
{
    __shared__ float As[16][65];
    __shared__ float Bs[16][65];
    const int bm = blockIdx.y * 64;
    const int bn = blockIdx.x * 64;
    const int tid = threadIdx.x;
    const int tr = tid / 16, tc = tid % 16;
    const int N = NOUTC, Kd = KC;

    float acc[4][4];
#pragma unroll
    for (int i = 0; i < 4; i++)
#pragma unroll
        for (int j = 0; j < 4; j++) acc[i][j] = 0.f;

    for (int k0 = 0; k0 < Kd; k0 += 16) {
        for (int l = tid; l < 64 * 16; l += 256) {
            int m = l / 16, k = l % 16;
            int kk = k0 + k;
            unsigned w = g_cbits[(size_t)(bm + m) * 4 + (kk >> 5)];
            As[k][m] = ((w >> (kk & 31)) & 1u) ? 1.f : 0.f;
        }
        for (int l = tid; l < 16 * 64; l += 256) {
            int k = l / 64, n = l % 64;
            Bs[k][n] = (bn + n < N) ? Bm[(size_t)(k0 + k) * N + bn + n] : 0.f;
        }
        __syncthreads();
#pragma unroll
        for (int k = 0; k < 16; k++) {
            float a[4], b[4];
#pragma unroll
            for (int i = 0; i < 4; i++) a[i] = As[k][tr * 4 + i];
#pragma unroll
            for (int j = 0; j < 4; j++) b[j] = Bs[k][tc * 4 + j];
#pragma unroll
            for (int i = 0; i < 4; i++)
#pragma unroll
                for (int j = 0; j < 4; j++)
                    acc[i][j] = fmaf(a[i], b[j], acc[i][j]);
        }
        __syncthreads();
    }
#pragma unroll
    for (int i = 0; i < 4; i++) {
        int m = bm + tr * 4 + i;
#pragma unroll
        for (int j = 0; j < 4; j++) {
            int n = bn + tc * 4 + j;
            if (n < N) g_logits[(size_t)m * N + n] = acc[i][j] + bias[n];
        }
    }
}

// ---------------- softmax: warp per (b,m) row, in-place probs ----------------
__global__ void __launch_bounds__(256) softmax_rows() {
    const int row  = blockIdx.x * 8 + (threadIdx.x >> 5);
    const int lane = threadIdx.x & 31;
    float* rp = g_logits + (size_t)row * NOUTC;

    float v[7];
#pragma unroll
    for (int k = 0; k < 7; k++) {
        int o = lane + 32 * k;
        v[k] = (o < NOUTC) ? rp[o] : -3.4e38f;
    }
    float mx = v[0];
#pragma unroll
    for (int k = 1; k < 7; k++) mx = fmaxf(mx, v[k]);
#pragma unroll
    for (int s = 16; s; s >>= 1) mx = fmaxf(mx, __shfl_xor_sync(0xffffffffu, mx, s));
    float sum = 0.f;
#pragma unroll
    for (int k = 0; k < 7; k++) {
        int o = lane + 32 * k;
        v[k] = (o < NOUTC) ? expf(v[k] - mx) : 0.f;
        sum += v[k];
    }
#pragma unroll
    for (int s = 16; s; s >>= 1) sum += __shfl_xor_sync(0xffffffffu, sum, s);
    float r = 1.f / sum;
#pragma unroll
    for (int k = 0; k < 7; k++) {
        int o = lane + 32 * k;
        if (o < NOUTC) rp[o] = v[k] * r;
    }
}

// ---------------- mean over m + log ----------------
__global__ void __launch_bounds__(256) mean_log(float* __restrict__ yp) {
    const int b = blockIdx.x;
    const int o = threadIdx.x;
    if (o >= NOUTC) return;
    const float* base = g_logits + (size_t)b * MC * NOUTC + o;
    float acc = 0.f;
#pragma unroll 4
    for (int m = 0; m < MC; m++) acc += base[(size_t)m * NOUTC];
    yp[(size_t)b * NOUTC + o] = logf(acc * (1.f / MC) + 1e-6f);
}

// ---------------- launch ----------------
extern "C" void kernel_launch(void* const* d_in, const int* in_sizes, int n_in,
                              void* d_out, int out_size) {
    const float* x     = (const float*)d_in[0];
    const float* Win   = (const float*)d_in[1];
    const float* binp  = (const float*)d_in[2];
    const float* Wh    = (const float*)d_in[3];
    const float* bh    = (const float*)d_in[4];
    const float* Wout  = (const float*)d_in[5];
    const float* bout  = (const float*)d_in[6];
    const float* pW1   = (const float*)d_in[7];
    const float* pb1   = (const float*)d_in[8];
    const float* pW2   = (const float*)d_in[9];
    const float* pb2   = (const float*)d_in[10];
    const float* hW    = (const float*)d_in[11];
    const float* hb    = (const float*)d_in[12];

    float* out    = (float*)d_out;
    float* c_prob = out;
    float* ypred  = out + (size_t)BN * KC * MC;
    float* c_hard = ypred + (size_t)BN * NOUTC;

    float *h0, *h1, *inter, *base;
    cudaGetSymbolAddress((void**)&h0,    g_h0);
    cudaGetSymbolAddress((void**)&h1,    g_h1);
    cudaGetSymbolAddress((void**)&inter, g_inter);
    cudaGetSymbolAddress((void**)&base,  g_base);

    init_kernel<<<256, 256>>>();

    // encoder (double-buffered SGEMM; identical fmaf k-order -> bit-identical inter)
    sgemm_bias_db<<<dim3(NHID/64, BN/64, 1), 256>>>(x,  Win, binp, h0, BN, NHID, CIN,  1);
    sgemm_bias_db<<<dim3(NHID/64, BN/64, 1), 256>>>(h0, Wh + 0*NHID*NHID, bh + 0*NHID, h1, BN, NHID, NHID, 1);
    sgemm_bias_db<<<dim3(NHID/64, BN/64, 1), 256>>>(h1, Wh + 1*NHID*NHID, bh + 1*NHID, h0, BN, NHID, NHID, 1);
    sgemm_bias_db<<<dim3(NHID/64, BN/64, 1), 256>>>(h0, Wh + 2*NHID*NHID, bh + 2*NHID, h1, BN, NHID, NHID, 1);
    sgemm_bias_db<<<dim3(NHID/64, BN/64, 1), 256>>>(h1, Wh + 3*NHID*NHID, bh + 3*NHID, h0, BN, NHID, NHID, 1);
    sgemm_bias_db<<<dim3(2, BN/64, 1), 256>>>(h0, Wout, bout, inter, BN, NF, NHID, 0);

    // all base vectors: base[i] = inter @ W1[i][:NF] + b1[i]  (batched over i; unchanged kernel)
    sgemm_bias<<<dim3(1, BN/64, KC), 256>>>(inter, pW1, pb1, base, BN, NL, NF, 0,
                                            0, (long)(NF + KC) * NL, NL, (long)BN * NL);

    // 112 sequential concept steps (2 pairs/thread, f32x2 FMA)
    for (int i = 0; i < KC; i++) {
        size_t shm = (size_t)i * 52 * sizeof(float);
        step2_kernel<<<(BN * MC) / 256, 128, shm>>>(i, pW1, pW2, pb2, c_prob, c_hard);
    }

    // head
    head_gemm<<<dim3((NOUTC + 63) / 64, (BN * MC) / 64, 1), 256>>>(hW, hb);
    softmax_rows<<<(BN * MC) / 8, 256>>>();
    mean_log<<<BN, 256>>>(ypred);
}